// round 10
// baseline (speedup 1.0000x reference)
#include <cuda_runtime.h>
#include <cuda.h>
#include <cstdint>
#include <math.h>

#define BLOCKT  64            // 64 threads = 64 samples per block
#define KDIM    784
#define TILE_K  112           // floats per tile: 448B contiguous per row visit
#define NT      7             // 7*112 = 784 exactly
#define RING    3
#define TILE_B  (64*TILE_K*4) // 28672 bytes per tile
// smem: xs 3*28672=86016 | mbars @86016 (32B) | w1s @86048 (12544B) | sw @98592 (960B)
#define SMEM_BYTES 99552

__device__ __forceinline__ void mbar_init1(unsigned addr) {
    asm volatile("mbarrier.init.shared.b64 [%0], 1;" :: "r"(addr) : "memory");
}
__device__ __forceinline__ void mbar_expect(unsigned addr, unsigned tx) {
    asm volatile("mbarrier.arrive.expect_tx.shared.b64 _, [%0], %1;"
                 :: "r"(addr), "r"(tx) : "memory");
}
__device__ __forceinline__ void mbar_wait(unsigned addr, unsigned parity) {
    asm volatile(
        "{\n\t.reg .pred P;\n\t"
        "WAIT_%=:\n\t"
        "mbarrier.try_wait.parity.acquire.cta.shared::cta.b64 P, [%0], %1, 0x989680;\n\t"
        "@P bra.uni DONE_%=;\n\t"
        "bra.uni WAIT_%=;\n\t"
        "DONE_%=:\n\t}"
        :: "r"(addr), "r"(parity) : "memory");
}
__device__ __forceinline__ void tma_2d(unsigned dst, const CUtensorMap* tm,
                                       int cx, int cy, unsigned mbar) {
    asm volatile(
        "cp.async.bulk.tensor.2d.shared::cta.global.tile.mbarrier::complete_tx::bytes "
        "[%0], [%1, {%2, %3}], [%4];"
        :: "r"(dst), "l"(tm), "r"(cx), "r"(cy), "r"(mbar) : "memory");
}

__global__ void __launch_bounds__(BLOCKT) qhybrid_kernel(
    const __grid_constant__ CUtensorMap tmap,
    const float* __restrict__ W1, const float* __restrict__ b1,
    const float* __restrict__ qw,
    const float* __restrict__ W2, const float* __restrict__ b2,
    const float* __restrict__ W3, const float* __restrict__ b3,
    float* __restrict__ out, int B)
{
    extern __shared__ __align__(1024) char smem[];
    char*  xs  = smem;                          // [3][64 rows][448B]
    float* w1s = (float*)(smem + 86048);        // [784][4]
    float* sw  = (float*)(smem + 98592);        // small weights

    const int tid = threadIdx.x;
    const unsigned smem_u = (unsigned)__cvta_generic_to_shared(smem);
    const unsigned mbar0  = smem_u + 86016u;

    // ---- tid 0: init ring mbarriers, kick off all 3 ring tiles ----
    if (tid == 0) {
        mbar_init1(mbar0);
        mbar_init1(mbar0 + 8);
        mbar_init1(mbar0 + 16);
        asm volatile("fence.proxy.async.shared::cta;" ::: "memory");
        const int rowbase = blockIdx.x * BLOCKT;
        #pragma unroll
        for (int t = 0; t < 3; t++) {
            mbar_expect(mbar0 + t * 8, TILE_B);
            tma_2d(smem_u + t * TILE_B, &tmap, t * TILE_K, rowbase, mbar0 + t * 8);
        }
    }

    // ---- preload W1 + small weights ----
    for (int r = tid; r < KDIM; r += BLOCKT)
        ((float4*)w1s)[r] = __ldg((const float4*)W1 + r);
    // b1@0(4) qw@4(8) W2@12(128) b2@140(32) W3@172(64) b3@236(2)
    if (tid < 4)  sw[tid]      = b1[tid];
    if (tid < 8)  sw[4 + tid]  = qw[tid];
    for (int j = tid; j < 128; j += BLOCKT) sw[12 + j] = W2[j];
    if (tid < 32) sw[140 + tid] = b2[tid];
    if (tid < 64) sw[172 + tid] = W3[tid];
    if (tid < 2)  sw[236 + tid] = b3[tid];
    __syncthreads();    // publish w1s/sw + mbar init

    float acc[4] = {0.f, 0.f, 0.f, 0.f};
    const char* xrow = xs + tid * (TILE_K * 4);   // this thread's row within a slot

    // ---- GEMM mainloop: 7 wide tiles, contiguous 448B row visits ----
    #pragma unroll 1
    for (int t = 0; t < NT; t++) {
        const int slot = t % RING;
        mbar_wait(mbar0 + (unsigned)(slot * 8), (unsigned)((t / RING) & 1));

        // compute tile t: 28 float4 chunks of this thread's row
        const float* xr = (const float*)(xrow + slot * TILE_B);
        const float* wb = w1s + t * TILE_K * 4;
        #pragma unroll
        for (int c = 0; c < 28; c++) {
            float4 xv = xr[0] == xr[0] ? ((const float4*)xr)[c] : make_float4(0,0,0,0);
            const float* wp = wb + c * 16;
            float4 wa = *(const float4*)(wp);
            float4 w2 = *(const float4*)(wp + 4);
            float4 w3 = *(const float4*)(wp + 8);
            float4 w4 = *(const float4*)(wp + 12);
            acc[0]=fmaf(xv.x,wa.x,acc[0]); acc[1]=fmaf(xv.x,wa.y,acc[1]);
            acc[2]=fmaf(xv.x,wa.z,acc[2]); acc[3]=fmaf(xv.x,wa.w,acc[3]);
            acc[0]=fmaf(xv.y,w2.x,acc[0]); acc[1]=fmaf(xv.y,w2.y,acc[1]);
            acc[2]=fmaf(xv.y,w2.z,acc[2]); acc[3]=fmaf(xv.y,w2.w,acc[3]);
            acc[0]=fmaf(xv.z,w3.x,acc[0]); acc[1]=fmaf(xv.z,w3.y,acc[1]);
            acc[2]=fmaf(xv.z,w3.z,acc[2]); acc[3]=fmaf(xv.z,w3.w,acc[3]);
            acc[0]=fmaf(xv.w,w4.x,acc[0]); acc[1]=fmaf(xv.w,w4.y,acc[1]);
            acc[2]=fmaf(xv.w,w4.z,acc[2]); acc[3]=fmaf(xv.w,w4.w,acc[3]);
        }

        __syncthreads();    // every thread done reading slot before reuse
        if (tid == 0 && t + RING < NT) {
            const int tp = t + RING;
            const unsigned mb = mbar0 + (unsigned)(slot * 8);
            mbar_expect(mb, TILE_B);
            tma_2d(smem_u + (unsigned)(slot * TILE_B), &tmap,
                   tp * TILE_K, blockIdx.x * BLOCKT, mb);
        }
    }

    // ---- angles = relu(pre + b1) ----
    float cq[4], sq[4];
    #pragma unroll
    for (int q = 0; q < 4; q++) {
        float ang = fmaxf(acc[q] + sw[q], 0.f);
        __sincosf(0.5f * ang, &sq[q], &cq[q]);
    }

    // ---- 4-qubit statevector in registers ----
    float re[16], im[16];
    #pragma unroll
    for (int i = 0; i < 16; i++) {
        float m = 1.f;
        #pragma unroll
        for (int q = 0; q < 4; q++) m *= ((i >> (3 - q)) & 1) ? sq[q] : cq[q];
        int k = __popc(i) & 3;  // phase (-i)^k
        re[i] = (k == 0) ? m : ((k == 2) ? -m : 0.f);
        im[i] = (k == 1) ? -m : ((k == 3) ? m : 0.f);
    }

    // ---- BasicEntanglerLayers: RX(w[l,q]) then CNOT ring ----
    #pragma unroll
    for (int l = 0; l < 2; l++) {
        #pragma unroll
        for (int q = 0; q < 4; q++) {
            float cg, sg;
            __sincosf(0.5f * sw[4 + l * 4 + q], &sg, &cg);
            const int mask = 8 >> q;
            #pragma unroll
            for (int i = 0; i < 16; i++) {
                if (i & mask) continue;
                const int i1 = i | mask;
                float r0 = re[i], ii0 = im[i], r1 = re[i1], ii1 = im[i1];
                re[i]  = fmaf(cg, r0,  sg * ii1);
                im[i]  = fmaf(cg, ii0, -sg * r1);
                re[i1] = fmaf(cg, r1,  sg * ii0);
                im[i1] = fmaf(cg, ii1, -sg * r0);
            }
        }
        #pragma unroll
        for (int q = 0; q < 4; q++) {
            const int cmask = 8 >> q;
            const int tmask = 8 >> ((q + 1) & 3);
            #pragma unroll
            for (int i = 0; i < 16; i++) {
                if ((i & cmask) && !(i & tmask)) {
                    const int j = i | tmask;
                    float t = re[i]; re[i] = re[j]; re[j] = t;
                    t = im[i]; im[i] = im[j]; im[j] = t;
                }
            }
        }
    }

    // ---- <Z_q> expectation values ----
    float ez[4] = {0.f, 0.f, 0.f, 0.f};
    #pragma unroll
    for (int i = 0; i < 16; i++) {
        float p = re[i] * re[i] + im[i] * im[i];
        #pragma unroll
        for (int q = 0; q < 4; q++)
            ez[q] += ((i >> (3 - q)) & 1) ? -p : p;
    }
    #pragma unroll
    for (int q = 0; q < 4; q++)
        if (!(ez[q] == ez[q])) ez[q] = 0.f;  // NaN -> 0 (matches reference)

    // ---- post = relu(ez@W2 + b2); logits = post@W3 + b3; softmax ----
    float l0 = sw[236], l1 = sw[237];
    #pragma unroll
    for (int j = 0; j < 32; j++) {
        float pj = sw[140 + j];
        #pragma unroll
        for (int q = 0; q < 4; q++)
            pj = fmaf(ez[q], sw[12 + q * 32 + j], pj);
        pj = fmaxf(pj, 0.f);
        l0 = fmaf(pj, sw[172 + j * 2],     l0);
        l1 = fmaf(pj, sw[172 + j * 2 + 1], l1);
    }
    float mx = fmaxf(l0, l1);
    float e0 = __expf(l0 - mx);
    float e1 = __expf(l1 - mx);
    float inv = 1.f / (e0 + e1);

    long sg = (long)blockIdx.x * BLOCKT + tid;
    if (sg < (long)B) {
        float2 o = make_float2(e0 * inv, e1 * inv);
        *(float2*)(out + sg * 2) = o;
    }
}

typedef CUresult (*PFN_encodeTiled)(
    CUtensorMap*, CUtensorMapDataType, cuuint32_t, void*,
    const cuuint64_t*, const cuuint64_t*, const cuuint32_t*, const cuuint32_t*,
    CUtensorMapInterleave, CUtensorMapSwizzle, CUtensorMapL2promotion,
    CUtensorMapFloatOOBfill);

extern "C" void kernel_launch(void* const* d_in, const int* in_sizes, int n_in,
                              void* d_out, int out_size) {
    const float* x  = (const float*)d_in[0];
    const float* W1 = (const float*)d_in[1];
    const float* b1 = (const float*)d_in[2];
    const float* qw = (const float*)d_in[3];
    const float* W2 = (const float*)d_in[4];
    const float* b2 = (const float*)d_in[5];
    const float* W3 = (const float*)d_in[6];
    const float* b3 = (const float*)d_in[7];
    float* out = (float*)d_out;

    int B = in_sizes[0] / KDIM;

    // Tensor map: x [B rows, 784 cols] fp32, box [112, 64], no swizzle.
    PFN_encodeTiled encode = nullptr;
    cudaDriverEntryPointQueryResult qres;
    cudaGetDriverEntryPoint("cuTensorMapEncodeTiled", (void**)&encode,
                            cudaEnableDefault, &qres);
    CUtensorMap tmap;
    cuuint64_t dims[2]    = {(cuuint64_t)KDIM, (cuuint64_t)B};
    cuuint64_t strides[1] = {(cuuint64_t)KDIM * sizeof(float)};
    cuuint32_t box[2]     = {TILE_K, BLOCKT};
    cuuint32_t estr[2]    = {1, 1};
    encode(&tmap, CU_TENSOR_MAP_DATA_TYPE_FLOAT32, 2, (void*)x,
           dims, strides, box, estr,
           CU_TENSOR_MAP_INTERLEAVE_NONE, CU_TENSOR_MAP_SWIZZLE_NONE,
           CU_TENSOR_MAP_L2_PROMOTION_L2_128B, CU_TENSOR_MAP_FLOAT_OOB_FILL_NONE);

    int grid = (B + BLOCKT - 1) / BLOCKT;           // 1024 blocks
    cudaFuncSetAttribute(qhybrid_kernel,
                         cudaFuncAttributeMaxDynamicSharedMemorySize, SMEM_BYTES);
    qhybrid_kernel<<<grid, BLOCKT, SMEM_BYTES>>>(tmap, W1, b1, qw, W2, b2, W3, b3, out, B);
}

// round 11
// speedup vs baseline: 1.1330x; 1.1330x over previous
#include <cuda_runtime.h>
#include <cstdint>
#include <math.h>

#define BLOCKT 128            // 4 warps; warp owns 32 samples (8 passes x 4)
#define KDIM   784

__device__ __forceinline__ float4 ldcg4(const float* p) {
    float4 v;
    asm volatile("ld.global.cg.v4.f32 {%0,%1,%2,%3}, [%4];"
                 : "=f"(v.x), "=f"(v.y), "=f"(v.z), "=f"(v.w) : "l"(p));
    return v;
}

__global__ void __launch_bounds__(BLOCKT) qhybrid_kernel(
    const float* __restrict__ x,
    const float* __restrict__ W1, const float* __restrict__ b1,
    const float* __restrict__ qw,
    const float* __restrict__ W2, const float* __restrict__ b2,
    const float* __restrict__ W3, const float* __restrict__ b3,
    float* __restrict__ out, int B)
{
    __shared__ float4 w1s[900];        // row r at slot r + (r>>3): bank-spread
    __shared__ float  sw[240];         // small weights
    __shared__ float4 ezb[4][32];      // per-warp ez staging

    const int tid  = threadIdx.x;
    const int lane = tid & 31;
    const int wrp  = tid >> 5;
    const int oct  = lane >> 3;        // which of 4 samples in this pass
    const int ol   = lane & 7;         // K-position within oct

    // ---- stage W1 (interleaved) + small weights ----
    for (int r = tid; r < KDIM; r += BLOCKT)
        w1s[r + (r >> 3)] = __ldg((const float4*)W1 + r);
    // b1@0(4) qw@4(8) W2@12(128) b2@140(32) W3@172(64) b3@236(2)
    if (tid < 4)   sw[tid]       = b1[tid];
    if (tid < 8)   sw[4 + tid]   = qw[tid];
    if (tid < 128) sw[12 + tid]  = W2[tid];
    if (tid < 32)  sw[140 + tid] = b2[tid];
    if (tid < 64)  sw[172 + tid] = W3[tid];
    if (tid < 2)   sw[236 + tid] = b3[tid];
    __syncthreads();   // only block-wide barrier

    const long wbase = (long)blockIdx.x * BLOCKT + wrp * 32;

    // ---- 8 passes: warp computes pre-activations for 4 samples per pass ----
    #pragma unroll 1
    for (int pass = 0; pass < 8; pass++) {
        long s = wbase + pass * 4 + oct;
        long sc = (s < (long)B) ? s : (long)(B - 1);   // clamp (loads stay legal)
        const float* xr = x + sc * (long)KDIM;

        float a0 = 0.f, a1 = 0.f, a2 = 0.f, a3 = 0.f;

        // 24 steps of 32 floats, in 4 batches of 6 (6 LDGs in flight per lane)
        #pragma unroll
        for (int bq = 0; bq < 4; bq++) {
            float4 xv[6];
            #pragma unroll
            for (int u = 0; u < 6; u++)
                xv[u] = ldcg4(xr + (bq * 6 + u) * 32 + ol * 4);
            #pragma unroll
            for (int u = 0; u < 6; u++) {
                const int kb = (bq * 6 + u) * 32 + ol * 4;
                const float xa[4] = {xv[u].x, xv[u].y, xv[u].z, xv[u].w};
                #pragma unroll
                for (int j = 0; j < 4; j++) {
                    const int r = kb + j;
                    float4 w = w1s[r + (r >> 3)];
                    a0 = fmaf(xa[j], w.x, a0);
                    a1 = fmaf(xa[j], w.y, a1);
                    a2 = fmaf(xa[j], w.z, a2);
                    a3 = fmaf(xa[j], w.w, a3);
                }
            }
        }
        // tail: floats 768..783 (rows 768 + 4*ol + j for ol < 4)
        if (ol < 4) {
            float4 xv = ldcg4(xr + 768 + ol * 4);
            const float xa[4] = {xv.x, xv.y, xv.z, xv.w};
            #pragma unroll
            for (int j = 0; j < 4; j++) {
                const int r = 768 + ol * 4 + j;
                float4 w = w1s[r + (r >> 3)];
                a0 = fmaf(xa[j], w.x, a0);
                a1 = fmaf(xa[j], w.y, a1);
                a2 = fmaf(xa[j], w.z, a2);
                a3 = fmaf(xa[j], w.w, a3);
            }
        }

        // reduce across the 8 oct lanes
        #pragma unroll
        for (int d = 1; d < 8; d <<= 1) {
            a0 += __shfl_xor_sync(0xFFFFFFFFu, a0, d);
            a1 += __shfl_xor_sync(0xFFFFFFFFu, a1, d);
            a2 += __shfl_xor_sync(0xFFFFFFFFu, a2, d);
            a3 += __shfl_xor_sync(0xFFFFFFFFu, a3, d);
        }
        if (ol == 0)
            ezb[wrp][pass * 4 + oct] = make_float4(a0, a1, a2, a3);
    }
    __syncwarp();

    // ---- epilogue: each lane handles sample wbase + lane ----
    float4 pre = ezb[wrp][lane];
    float acc[4] = {pre.x, pre.y, pre.z, pre.w};

    // angles = relu(pre + b1)
    float cq[4], sq[4];
    #pragma unroll
    for (int q = 0; q < 4; q++) {
        float ang = fmaxf(acc[q] + sw[q], 0.f);
        __sincosf(0.5f * ang, &sq[q], &cq[q]);
    }

    // 4-qubit statevector in registers
    float re[16], im[16];
    #pragma unroll
    for (int i = 0; i < 16; i++) {
        float m = 1.f;
        #pragma unroll
        for (int q = 0; q < 4; q++) m *= ((i >> (3 - q)) & 1) ? sq[q] : cq[q];
        int k = __popc(i) & 3;  // phase (-i)^k
        re[i] = (k == 0) ? m : ((k == 2) ? -m : 0.f);
        im[i] = (k == 1) ? -m : ((k == 3) ? m : 0.f);
    }

    // BasicEntanglerLayers: RX(w[l,q]) then CNOT ring
    #pragma unroll
    for (int l = 0; l < 2; l++) {
        #pragma unroll
        for (int q = 0; q < 4; q++) {
            float cg, sg;
            __sincosf(0.5f * sw[4 + l * 4 + q], &sg, &cg);
            const int mask = 8 >> q;
            #pragma unroll
            for (int i = 0; i < 16; i++) {
                if (i & mask) continue;
                const int i1 = i | mask;
                float r0 = re[i], ii0 = im[i], r1 = re[i1], ii1 = im[i1];
                re[i]  = fmaf(cg, r0,  sg * ii1);
                im[i]  = fmaf(cg, ii0, -sg * r1);
                re[i1] = fmaf(cg, r1,  sg * ii0);
                im[i1] = fmaf(cg, ii1, -sg * r0);
            }
        }
        #pragma unroll
        for (int q = 0; q < 4; q++) {
            const int cmask = 8 >> q;
            const int tmask = 8 >> ((q + 1) & 3);
            #pragma unroll
            for (int i = 0; i < 16; i++) {
                if ((i & cmask) && !(i & tmask)) {
                    const int j = i | tmask;
                    float t = re[i]; re[i] = re[j]; re[j] = t;
                    t = im[i]; im[i] = im[j]; im[j] = t;
                }
            }
        }
    }

    // <Z_q> expectation values
    float ez[4] = {0.f, 0.f, 0.f, 0.f};
    #pragma unroll
    for (int i = 0; i < 16; i++) {
        float p = re[i] * re[i] + im[i] * im[i];
        #pragma unroll
        for (int q = 0; q < 4; q++)
            ez[q] += ((i >> (3 - q)) & 1) ? -p : p;
    }
    #pragma unroll
    for (int q = 0; q < 4; q++)
        if (!(ez[q] == ez[q])) ez[q] = 0.f;  // NaN -> 0 (matches reference)

    // post = relu(ez@W2 + b2); logits = post@W3 + b3; softmax
    float l0 = sw[236], l1 = sw[237];
    #pragma unroll
    for (int j = 0; j < 32; j++) {
        float pj = sw[140 + j];
        #pragma unroll
        for (int q = 0; q < 4; q++)
            pj = fmaf(ez[q], sw[12 + q * 32 + j], pj);
        pj = fmaxf(pj, 0.f);
        l0 = fmaf(pj, sw[172 + j * 2],     l0);
        l1 = fmaf(pj, sw[172 + j * 2 + 1], l1);
    }
    float mx = fmaxf(l0, l1);
    float e0 = __expf(l0 - mx);
    float e1 = __expf(l1 - mx);
    float inv = 1.f / (e0 + e1);

    long sg = wbase + lane;
    if (sg < (long)B) {
        float2 o = make_float2(e0 * inv, e1 * inv);
        *(float2*)(out + sg * 2) = o;
    }
}

extern "C" void kernel_launch(void* const* d_in, const int* in_sizes, int n_in,
                              void* d_out, int out_size) {
    const float* x  = (const float*)d_in[0];
    const float* W1 = (const float*)d_in[1];
    const float* b1 = (const float*)d_in[2];
    const float* qw = (const float*)d_in[3];
    const float* W2 = (const float*)d_in[4];
    const float* b2 = (const float*)d_in[5];
    const float* W3 = (const float*)d_in[6];
    const float* b3 = (const float*)d_in[7];
    float* out = (float*)d_out;

    int B = in_sizes[0] / KDIM;
    int grid = (B + BLOCKT - 1) / BLOCKT;   // 512 blocks, all resident
    qhybrid_kernel<<<grid, BLOCKT>>>(x, W1, b1, qw, W2, b2, W3, b3, out, B);
}

// round 12
// speedup vs baseline: 1.2746x; 1.1250x over previous
#include <cuda_runtime.h>
#include <cuda.h>
#include <cstdint>
#include <math.h>

#define BLOCKT  64            // 64 threads = 64 samples per block
#define KDIM    784
#define KPAD    800
#define TILE_K  32            // 32 cols * 4B = 128B rows (SW128 box)
#define NT      25            // 25*32 = 800 (TMA zero-fills cols >= 784)
#define RING    4
#define TILE_B  8192          // 64 rows * 128B
// smem bytes: xs 4*8192 = 32768 | mbars @32768 (32B) | w1s @32800 (12800B) | sw @45600 (960B)
#define SMEM_BYTES 46560

__device__ __forceinline__ void mbar_init1(unsigned addr) {
    asm volatile("mbarrier.init.shared.b64 [%0], 1;" :: "r"(addr) : "memory");
}
__device__ __forceinline__ void mbar_expect(unsigned addr, unsigned tx) {
    asm volatile("mbarrier.arrive.expect_tx.shared.b64 _, [%0], %1;"
                 :: "r"(addr), "r"(tx) : "memory");
}
__device__ __forceinline__ void mbar_wait(unsigned addr, unsigned parity) {
    asm volatile(
        "{\n\t.reg .pred P;\n\t"
        "WAIT_%=:\n\t"
        "mbarrier.try_wait.parity.acquire.cta.shared::cta.b64 P, [%0], %1, 0x989680;\n\t"
        "@P bra.uni DONE_%=;\n\t"
        "bra.uni WAIT_%=;\n\t"
        "DONE_%=:\n\t}"
        :: "r"(addr), "r"(parity) : "memory");
}
__device__ __forceinline__ void tma_2d(unsigned dst, const CUtensorMap* tm,
                                       int cx, int cy, unsigned mbar) {
    asm volatile(
        "cp.async.bulk.tensor.2d.shared::cta.global.tile.mbarrier::complete_tx::bytes "
        "[%0], [%1, {%2, %3}], [%4];"
        :: "r"(dst), "l"(tm), "r"(cx), "r"(cy), "r"(mbar) : "memory");
}

__global__ void __launch_bounds__(BLOCKT) qhybrid_kernel(
    const __grid_constant__ CUtensorMap tmap,
    const float* __restrict__ W1, const float* __restrict__ b1,
    const float* __restrict__ qw,
    const float* __restrict__ W2, const float* __restrict__ b2,
    const float* __restrict__ W3, const float* __restrict__ b3,
    float* __restrict__ out, int B)
{
    extern __shared__ __align__(1024) char smem[];
    char*  xs  = smem;                          // [4][64 rows][128B] swizzled
    float* w1s = (float*)(smem + 32800);        // [800][4]
    float* sw  = (float*)(smem + 45600);        // small weights

    const int tid = threadIdx.x;
    const unsigned smem_u = (unsigned)__cvta_generic_to_shared(smem);
    const unsigned mbar0  = smem_u + 32768u;    // 4 mbars * 8B

    // ---- tid 0: init ring mbarriers, kick off 3 tiles immediately ----
    if (tid == 0) {
        mbar_init1(mbar0);
        mbar_init1(mbar0 + 8);
        mbar_init1(mbar0 + 16);
        mbar_init1(mbar0 + 24);
        asm volatile("fence.proxy.async.shared::cta;" ::: "memory");
        const int rowbase = blockIdx.x * BLOCKT;
        #pragma unroll
        for (int kt = 0; kt < 3; kt++) {
            mbar_expect(mbar0 + kt * 8, TILE_B);
            tma_2d(smem_u + kt * TILE_B, &tmap, kt * TILE_K, rowbase, mbar0 + kt * 8);
        }
    }

    // ---- preload W1 (zero-padded rows 784..799) + small weights ----
    for (int r = tid; r < KPAD; r += BLOCKT) {
        float4 v = make_float4(0.f, 0.f, 0.f, 0.f);
        if (r < KDIM) v = __ldg((const float4*)W1 + r);
        ((float4*)w1s)[r] = v;
    }
    // b1@0(4) qw@4(8) W2@12(128) b2@140(32) W3@172(64) b3@236(2)
    if (tid < 4)  sw[tid]      = b1[tid];
    if (tid < 8)  sw[4 + tid]  = qw[tid];
    for (int j = tid; j < 128; j += BLOCKT) sw[12 + j] = W2[j];
    if (tid < 32) sw[140 + tid] = b2[tid];
    for (int j = tid; j < 64; j += BLOCKT)  sw[172 + j] = W3[j];
    if (tid < 2)  sw[236 + tid] = b3[tid];
    __syncthreads();    // publish w1s/sw; orders mbar init for all threads

    float acc[4] = {0.f, 0.f, 0.f, 0.f};
    const int rsw = (tid & 7);          // swizzle key for this thread's row
    char* xrow_base = xs + tid * 128;   // + slot*TILE_B

    // ---- GEMM mainloop: TMA ring, one barrier per iter ----
    #pragma unroll 1
    for (int kt = 0; kt < NT; kt++) {
        mbar_wait(mbar0 + (unsigned)((kt & 3) * 8), (unsigned)((kt >> 2) & 1));
        __syncthreads();   // all warps done with tile kt-1's slot reads; tile kt visible

        if (tid == 0) {
            const int kp = kt + 3;
            if (kp < NT) {
                const unsigned mb = mbar0 + (unsigned)((kp & 3) * 8);
                mbar_expect(mb, TILE_B);
                tma_2d(smem_u + (unsigned)((kp & 3) * TILE_B), &tmap,
                       kp * TILE_K, blockIdx.x * BLOCKT, mb);
            }
        }

        // compute tile kt: 8 swizzled float4 chunks of this thread's row
        const char* xr = xrow_base + (kt & 3) * TILE_B;
        const float* wb = w1s + kt * TILE_K * 4;
        #pragma unroll
        for (int j = 0; j < 8; j++) {
            float4 xv = *(const float4*)(xr + ((j ^ rsw) << 4));
            const float* wp = wb + j * 16;
            float4 wa = *(const float4*)(wp);
            float4 w2 = *(const float4*)(wp + 4);
            float4 w3 = *(const float4*)(wp + 8);
            float4 w4 = *(const float4*)(wp + 12);
            acc[0]=fmaf(xv.x,wa.x,acc[0]); acc[1]=fmaf(xv.x,wa.y,acc[1]);
            acc[2]=fmaf(xv.x,wa.z,acc[2]); acc[3]=fmaf(xv.x,wa.w,acc[3]);
            acc[0]=fmaf(xv.y,w2.x,acc[0]); acc[1]=fmaf(xv.y,w2.y,acc[1]);
            acc[2]=fmaf(xv.y,w2.z,acc[2]); acc[3]=fmaf(xv.y,w2.w,acc[3]);
            acc[0]=fmaf(xv.z,w3.x,acc[0]); acc[1]=fmaf(xv.z,w3.y,acc[1]);
            acc[2]=fmaf(xv.z,w3.z,acc[2]); acc[3]=fmaf(xv.z,w3.w,acc[3]);
            acc[0]=fmaf(xv.w,w4.x,acc[0]); acc[1]=fmaf(xv.w,w4.y,acc[1]);
            acc[2]=fmaf(xv.w,w4.z,acc[2]); acc[3]=fmaf(xv.w,w4.w,acc[3]);
        }
    }

    // ---- angles = relu(pre + b1) ----
    float cq[4], sq[4];
    #pragma unroll
    for (int q = 0; q < 4; q++) {
        float ang = fmaxf(acc[q] + sw[q], 0.f);
        __sincosf(0.5f * ang, &sq[q], &cq[q]);
    }

    // ---- 4-qubit statevector in registers ----
    float re[16], im[16];
    #pragma unroll
    for (int i = 0; i < 16; i++) {
        float m = 1.f;
        #pragma unroll
        for (int q = 0; q < 4; q++) m *= ((i >> (3 - q)) & 1) ? sq[q] : cq[q];
        int k = __popc(i) & 3;  // phase (-i)^k
        re[i] = (k == 0) ? m : ((k == 2) ? -m : 0.f);
        im[i] = (k == 1) ? -m : ((k == 3) ? m : 0.f);
    }

    // ---- BasicEntanglerLayers: RX(w[l,q]) then CNOT ring ----
    #pragma unroll
    for (int l = 0; l < 2; l++) {
        #pragma unroll
        for (int q = 0; q < 4; q++) {
            float cg, sg;
            __sincosf(0.5f * sw[4 + l * 4 + q], &sg, &cg);
            const int mask = 8 >> q;
            #pragma unroll
            for (int i = 0; i < 16; i++) {
                if (i & mask) continue;
                const int i1 = i | mask;
                float r0 = re[i], ii0 = im[i], r1 = re[i1], ii1 = im[i1];
                re[i]  = fmaf(cg, r0,  sg * ii1);
                im[i]  = fmaf(cg, ii0, -sg * r1);
                re[i1] = fmaf(cg, r1,  sg * ii0);
                im[i1] = fmaf(cg, ii1, -sg * r0);
            }
        }
        #pragma unroll
        for (int q = 0; q < 4; q++) {
            const int cmask = 8 >> q;
            const int tmask = 8 >> ((q + 1) & 3);
            #pragma unroll
            for (int i = 0; i < 16; i++) {
                if ((i & cmask) && !(i & tmask)) {
                    const int j = i | tmask;
                    float t = re[i]; re[i] = re[j]; re[j] = t;
                    t = im[i]; im[i] = im[j]; im[j] = t;
                }
            }
        }
    }

    // ---- <Z_q> expectation values ----
    float ez[4] = {0.f, 0.f, 0.f, 0.f};
    #pragma unroll
    for (int i = 0; i < 16; i++) {
        float p = re[i] * re[i] + im[i] * im[i];
        #pragma unroll
        for (int q = 0; q < 4; q++)
            ez[q] += ((i >> (3 - q)) & 1) ? -p : p;
    }
    #pragma unroll
    for (int q = 0; q < 4; q++)
        if (!(ez[q] == ez[q])) ez[q] = 0.f;  // NaN -> 0 (matches reference)

    // ---- post = relu(ez@W2 + b2); logits = post@W3 + b3; softmax ----
    float l0 = sw[236], l1 = sw[237];
    #pragma unroll
    for (int j = 0; j < 32; j++) {
        float pj = sw[140 + j];
        #pragma unroll
        for (int q = 0; q < 4; q++)
            pj = fmaf(ez[q], sw[12 + q * 32 + j], pj);
        pj = fmaxf(pj, 0.f);
        l0 = fmaf(pj, sw[172 + j * 2],     l0);
        l1 = fmaf(pj, sw[172 + j * 2 + 1], l1);
    }
    float mx = fmaxf(l0, l1);
    float e0 = __expf(l0 - mx);
    float e1 = __expf(l1 - mx);
    float inv = 1.f / (e0 + e1);

    long sg = (long)blockIdx.x * BLOCKT + tid;
    if (sg < (long)B) {
        float2 o = make_float2(e0 * inv, e1 * inv);
        *(float2*)(out + sg * 2) = o;
    }
}

typedef CUresult (*PFN_encodeTiled)(
    CUtensorMap*, CUtensorMapDataType, cuuint32_t, void*,
    const cuuint64_t*, const cuuint64_t*, const cuuint32_t*, const cuuint32_t*,
    CUtensorMapInterleave, CUtensorMapSwizzle, CUtensorMapL2promotion,
    CUtensorMapFloatOOBfill);

extern "C" void kernel_launch(void* const* d_in, const int* in_sizes, int n_in,
                              void* d_out, int out_size) {
    const float* x  = (const float*)d_in[0];
    const float* W1 = (const float*)d_in[1];
    const float* b1 = (const float*)d_in[2];
    const float* qw = (const float*)d_in[3];
    const float* W2 = (const float*)d_in[4];
    const float* b2 = (const float*)d_in[5];
    const float* W3 = (const float*)d_in[6];
    const float* b3 = (const float*)d_in[7];
    float* out = (float*)d_out;

    int B = in_sizes[0] / KDIM;

    // Tensor map for x: [B rows, 784 cols] fp32, box [32, 64], SW128,
    // L2 promotion 256B -> each DRAM miss also fetches the NEXT K-tile's
    // chunk for the same row (consumed 1-2 iterations later from L2).
    PFN_encodeTiled encode = nullptr;
    cudaDriverEntryPointQueryResult qres;
    cudaGetDriverEntryPoint("cuTensorMapEncodeTiled", (void**)&encode,
                            cudaEnableDefault, &qres);
    CUtensorMap tmap;
    cuuint64_t dims[2]    = {(cuuint64_t)KDIM, (cuuint64_t)B};
    cuuint64_t strides[1] = {(cuuint64_t)KDIM * sizeof(float)};
    cuuint32_t box[2]     = {TILE_K, BLOCKT};
    cuuint32_t estr[2]    = {1, 1};
    encode(&tmap, CU_TENSOR_MAP_DATA_TYPE_FLOAT32, 2, (void*)x,
           dims, strides, box, estr,
           CU_TENSOR_MAP_INTERLEAVE_NONE, CU_TENSOR_MAP_SWIZZLE_128B,
           CU_TENSOR_MAP_L2_PROMOTION_L2_256B, CU_TENSOR_MAP_FLOAT_OOB_FILL_NONE);

    int grid = (B + BLOCKT - 1) / BLOCKT;           // 1024 blocks
    cudaFuncSetAttribute(qhybrid_kernel,
                         cudaFuncAttributeMaxDynamicSharedMemorySize, SMEM_BYTES);
    qhybrid_kernel<<<grid, BLOCKT, SMEM_BYTES>>>(tmap, W1, b1, qw, W2, b2, W3, b3, out, B);
}